// round 7
// baseline (speedup 1.0000x reference)
#include <cuda_runtime.h>
#include <cstdint>

// Padded per-node projections: row stride 32 floats.
//   [n*32 + 0..9]   = h[n].W_u[c]  (src half of W)
//   [n*32 + 16..25] = h[n].W_v[c]  (dst half of W)
#define N_NODES_MAX 100000
__device__ __align__(128) float g_P[N_NODES_MAX * 32];
__device__ int g_idx_is64;

__device__ __forceinline__ float2 ffma2(float2 a, float2 b, float2 c) {
    float2 d;
    asm("{\n\t"
        ".reg .b64 ra, rb, rc, rd;\n\t"
        "mov.b64 ra, {%2, %3};\n\t"
        "mov.b64 rb, {%4, %5};\n\t"
        "mov.b64 rc, {%6, %7};\n\t"
        "fma.rn.f32x2 rd, ra, rb, rc;\n\t"
        "mov.b64 {%0, %1}, rd;\n\t"
        "}"
        : "=f"(d.x), "=f"(d.y)
        : "f"(a.x), "f"(a.y), "f"(b.x), "f"(b.y), "f"(c.x), "f"(c.y));
    return d;
}

// ---------------------------------------------------------------------------
// Node kernel: warp tiles of 8 nodes, lane=(nsub,q). No dynamic smem, no
// barriers in the loop — x comes straight from L1 (one private 128B line per
// lane per tile). Also performs the index-dtype probe.
// ---------------------------------------------------------------------------
__global__ __launch_bounds__(256, 4) void node_kernel(
    const float* __restrict__ h, const float* __restrict__ W_w,
    const long long* __restrict__ src_probe, int n_nodes) {
    __shared__ float4 sWa[320];   // [j8][p10][q4] even channels
    __shared__ float4 sWb[320];   // odd channels
    int tid = threadIdx.x, wid = tid >> 5, lane = tid & 31;

    if (blockIdx.x == 0 && tid == 0) {   // dtype probe (runs before edge kernel)
        int is64 = 1;
        for (int i = 0; i < 8; i++)
            if ((unsigned long long)src_probe[i] >> 32) is64 = 0;
        g_idx_is64 = is64;
    }

    for (int i = tid; i < 320; i += 256) {
        int j = i / 40, r = i % 40, p = r / 4, qq = r % 4;
        int base = (p < 5) ? 0 : 128;
        int c0   = (p < 5) ? 2 * p : 2 * (p - 5);
        int col  = base + qq * 32 + j * 4;
        const float* w0 = W_w + c0 * 384 + col;
        const float* w1 = W_w + (c0 + 1) * 384 + col;
        sWa[i] = make_float4(w0[0], w0[1], w0[2], w0[3]);
        sWb[i] = make_float4(w1[0], w1[1], w1[2], w1[3]);
    }
    __syncthreads();

    int q = lane & 3, nsub = lane >> 2;
    long long T  = ((long long)n_nodes + 7) >> 3;
    long long gw = (long long)blockIdx.x * 8 + wid;
    long long nw = (long long)gridDim.x * 8;

    for (long long t = gw; t < T; t += nw) {
        long long n = t * 8 + nsub;
        long long nSafe = (n < n_nodes) ? n : 0;
        const float4* xr = (const float4*)h + nSafe * 32 + q * 8;

        float2 acc[10];
#pragma unroll
        for (int p = 0; p < 10; p++) acc[p] = make_float2(0.f, 0.f);

#pragma unroll
        for (int jc = 0; jc < 4; jc++) {
            float4 xv[2];
#pragma unroll
            for (int jj = 0; jj < 2; jj++) xv[jj] = __ldg(xr + jc * 2 + jj);
#pragma unroll
            for (int jj = 0; jj < 2; jj++) {
                int j = jc * 2 + jj;
                float4 x = xv[jj];
#pragma unroll
                for (int p = 0; p < 10; p++) {
                    float4 wa = sWa[j * 40 + p * 4 + q];
                    float4 wb = sWb[j * 40 + p * 4 + q];
                    acc[p] = ffma2(make_float2(x.x, x.x), make_float2(wa.x, wb.x), acc[p]);
                    acc[p] = ffma2(make_float2(x.y, x.y), make_float2(wa.y, wb.y), acc[p]);
                    acc[p] = ffma2(make_float2(x.z, x.z), make_float2(wa.z, wb.z), acc[p]);
                    acc[p] = ffma2(make_float2(x.w, x.w), make_float2(wa.w, wb.w), acc[p]);
                }
            }
        }
#pragma unroll
        for (int off = 1; off <= 2; off <<= 1)
#pragma unroll
            for (int p = 0; p < 10; p++) {
                acc[p].x += __shfl_xor_sync(0xffffffffu, acc[p].x, off);
                acc[p].y += __shfl_xor_sync(0xffffffffu, acc[p].y, off);
            }

        if (n < n_nodes) {
            float2 pa = acc[0], pb = acc[5];
            if (q == 1) { pa = acc[1]; pb = acc[6]; }
            if (q == 2) { pa = acc[2]; pb = acc[7]; }
            if (q == 3) { pa = acc[3]; pb = acc[8]; }
            float* row = g_P + n * 32;
            *(float2*)(row + 2 * q)      = pa;
            *(float2*)(row + 16 + 2 * q) = pb;
            if (q == 0) {
                *(float2*)(row + 8)  = acc[4];
                *(float2*)(row + 24) = acc[9];
            }
        }
    }
}

// ---------------------------------------------------------------------------
// Edge kernel: warp tiles of 8 edges, lane=(esub,q). No dynamic smem, no
// barriers. out[e][c] = edge_h[e].W_e[c] + P[src][c] + P[dst][16+c] + b[c]
// ---------------------------------------------------------------------------
__global__ __launch_bounds__(256, 5) void edge_kernel(
    const float* __restrict__ eh, const float* __restrict__ W_w,
    const float* __restrict__ W_b,
    const void* __restrict__ src_raw, const void* __restrict__ dst_raw,
    float* __restrict__ out, int n_edges) {
    __shared__ float4 sWa[160];   // [j8][p5][q4] even channels
    __shared__ float4 sWb[160];   // odd channels
    int tid = threadIdx.x, wid = tid >> 5, lane = tid & 31;

    for (int i = tid; i < 160; i += 256) {
        int j = i / 20, r = i % 20, p = r / 4, qq = r % 4;
        int col = 256 + qq * 32 + j * 4;
        const float* w0 = W_w + (2 * p) * 384 + col;
        const float* w1 = W_w + (2 * p + 1) * 384 + col;
        sWa[i] = make_float4(w0[0], w0[1], w0[2], w0[3]);
        sWb[i] = make_float4(w1[0], w1[1], w1[2], w1[3]);
    }
    __syncthreads();

    int q = lane & 3, esub = lane >> 2;
    int is64 = g_idx_is64;
    float2 bq = make_float2(__ldg(W_b + 2 * q), __ldg(W_b + 2 * q + 1));
    float2 b4 = make_float2(__ldg(W_b + 8), __ldg(W_b + 9));

    long long T  = ((long long)n_edges + 7) >> 3;
    long long gw = (long long)blockIdx.x * 8 + wid;
    long long nw = (long long)gridDim.x * 8;

    for (long long t = gw; t < T; t += nw) {
        long long e = t * 8 + esub;
        long long eSafe = (e < n_edges) ? e : 0;
        const float4* xr = (const float4*)eh + eSafe * 32 + q * 8;

        float2 acc[5];
#pragma unroll
        for (int p = 0; p < 5; p++) acc[p] = make_float2(0.f, 0.f);

#pragma unroll
        for (int jc = 0; jc < 2; jc++) {
            float4 xv[4];
#pragma unroll
            for (int jj = 0; jj < 4; jj++) xv[jj] = __ldg(xr + jc * 4 + jj);
#pragma unroll
            for (int jj = 0; jj < 4; jj++) {
                int j = jc * 4 + jj;
                float4 x = xv[jj];
#pragma unroll
                for (int p = 0; p < 5; p++) {
                    float4 wa = sWa[j * 20 + p * 4 + q];
                    float4 wb = sWb[j * 20 + p * 4 + q];
                    acc[p] = ffma2(make_float2(x.x, x.x), make_float2(wa.x, wb.x), acc[p]);
                    acc[p] = ffma2(make_float2(x.y, x.y), make_float2(wa.y, wb.y), acc[p]);
                    acc[p] = ffma2(make_float2(x.z, x.z), make_float2(wa.z, wb.z), acc[p]);
                    acc[p] = ffma2(make_float2(x.w, x.w), make_float2(wa.w, wb.w), acc[p]);
                }
            }
        }
#pragma unroll
        for (int off = 1; off <= 2; off <<= 1)
#pragma unroll
            for (int p = 0; p < 5; p++) {
                acc[p].x += __shfl_xor_sync(0xffffffffu, acc[p].x, off);
                acc[p].y += __shfl_xor_sync(0xffffffffu, acc[p].y, off);
            }

        if (e < n_edges) {
            long long sN, dN;
            if (is64) {
                sN = ((const long long*)src_raw)[e];
                dN = ((const long long*)dst_raw)[e];
            } else {
                sN = ((const int*)src_raw)[e];
                dN = ((const int*)dst_raw)[e];
            }
            const float2* pu = (const float2*)(g_P + sN * 32);
            const float2* pv = (const float2*)(g_P + dN * 32 + 16);
            float2 mya = acc[0];
            if (q == 1) mya = acc[1];
            if (q == 2) mya = acc[2];
            if (q == 3) mya = acc[3];
            float2 gu = __ldg(pu + q);
            float2 gv = __ldg(pv + q);
            *(float2*)(out + e * 10 + 2 * q) =
                make_float2(mya.x + gu.x + gv.x + bq.x,
                            mya.y + gu.y + gv.y + bq.y);
            if (q == 0) {
                float2 gu4 = __ldg(pu + 4);
                float2 gv4 = __ldg(pv + 4);
                *(float2*)(out + e * 10 + 8) =
                    make_float2(acc[4].x + gu4.x + gv4.x + b4.x,
                                acc[4].y + gu4.y + gv4.y + b4.y);
            }
        }
    }
}

// ---------------------------------------------------------------------------
// Inputs: h [100000,128] f32, edge_h [600000,1,128] f32, W_w [10,384] f32,
// W_b [10] f32, src [600000] int32/64, dst [600000] int32/64.
// Output: [600000,10] f32.
// ---------------------------------------------------------------------------
extern "C" void kernel_launch(void* const* d_in, const int* in_sizes, int n_in,
                              void* d_out, int out_size) {
    const float* h   = (const float*)d_in[0];
    const float* eh  = (const float*)d_in[1];
    const float* W_w = (const float*)d_in[2];
    const float* W_b = (const float*)d_in[3];
    const void*  src = d_in[4];
    const void*  dst = d_in[5];
    float*       out = (float*)d_out;

    int n_nodes = in_sizes[0] / 128;
    int n_edges = in_sizes[4];

    node_kernel<<<592, 256>>>(h, W_w, (const long long*)src, n_nodes);
    edge_kernel<<<740, 256>>>(eh, W_w, W_b, src, dst, out, n_edges);
}

// round 11
// speedup vs baseline: 1.1826x; 1.1826x over previous
#include <cuda_runtime.h>
#include <cstdint>

// Padded per-node projections: row stride 32 floats.
//   [n*32 + 0..9]   = h[n].W_u[c]  (src half of W)
//   [n*32 + 16..25] = h[n].W_v[c]  (dst half of W)
#define N_NODES_MAX 100000
__device__ __align__(128) float g_P[N_NODES_MAX * 32];
__device__ int g_idx_is64;

__device__ __forceinline__ float2 ffma2(float2 a, float2 b, float2 c) {
    float2 d;
    asm("{\n\t"
        ".reg .b64 ra, rb, rc, rd;\n\t"
        "mov.b64 ra, {%2, %3};\n\t"
        "mov.b64 rb, {%4, %5};\n\t"
        "mov.b64 rc, {%6, %7};\n\t"
        "fma.rn.f32x2 rd, ra, rb, rc;\n\t"
        "mov.b64 {%0, %1}, rd;\n\t"
        "}"
        : "=f"(d.x), "=f"(d.y)
        : "f"(a.x), "f"(a.y), "f"(b.x), "f"(b.y), "f"(c.x), "f"(c.y));
    return d;
}

__device__ __forceinline__ float shx(float v, int m) {
    return __shfl_xor_sync(0xffffffffu, v, m);
}

// ===========================================================================
// Node kernel. Warp tile = 4 nodes. Lane l owns columns 4l..4l+3 of W_u/W_v
// (40 float2 in registers). Coalesced LDG gives lane l exactly its column
// chunk of each node. 20-channel sum via 21-shfl channel-splitting butterfly.
// ===========================================================================
__global__ __launch_bounds__(128) void node_kernel(
    const float* __restrict__ h, const float* __restrict__ W_w,
    const long long* __restrict__ src_probe, int n_nodes) {
    int tid = threadIdx.x, lane = tid & 31;

    if (blockIdx.x == 0 && tid == 0) {   // index-dtype probe
        int is64 = 1;
        for (int i = 0; i < 8; i++)
            if ((unsigned long long)src_probe[i] >> 32) is64 = 0;
        g_idx_is64 = is64;
    }

    // register weights: wu/wv[d][p] = channels (2p, 2p+1), column 4*lane+d
    float2 wu[4][5], wv[4][5];
#pragma unroll
    for (int d = 0; d < 4; d++)
#pragma unroll
        for (int p = 0; p < 5; p++) {
            int col = 4 * lane + d;
            wu[d][p] = make_float2(__ldg(W_w + (2 * p) * 384 + col),
                                   __ldg(W_w + (2 * p + 1) * 384 + col));
            wv[d][p] = make_float2(__ldg(W_w + (2 * p) * 384 + 128 + col),
                                   __ldg(W_w + (2 * p + 1) * 384 + 128 + col));
        }

    bool b4h = lane & 16, b3h = lane & 8, b2h = lane & 4, b1h = lane & 2,
         b0h = lane & 1;
    int inner = (!b2h) ? ((!b1h) ? (b0h ? 1 : 0) : 2) : ((!b1h) ? 3 : 4);
    int ch    = (b4h ? 10 : 0) + (b3h ? 5 : 0) + inner;
    bool rep  = (!b2h && !b1h) ? true : !b0h;
    int off   = (ch < 10) ? ch : ch + 6;   // V block starts at +16

    int T = (n_nodes + 3) >> 2;
    int gw = (blockIdx.x * 128 + tid) >> 5;
    int stride = (gridDim.x * 128) >> 5;
    int maxF4 = n_nodes * 32 - 1;
    const float4* hp = (const float4*)h;

    int t = gw;
    float4 xc[4];
    if (t < T) {
#pragma unroll
        for (int i = 0; i < 4; i++)
            xc[i] = __ldg(hp + min(t * 128 + i * 32 + lane, maxF4));
    }
    for (; t < T; t += stride) {
        int tn = t + stride;
        float4 xn[4];
        if (tn < T) {
#pragma unroll
            for (int i = 0; i < 4; i++)
                xn[i] = __ldg(hp + min(tn * 128 + i * 32 + lane, maxF4));
        }
#pragma unroll
        for (int i = 0; i < 4; i++) {
            int n = t * 4 + i;
            float4 x = xc[i];
            float2 aU[5], aV[5];
#pragma unroll
            for (int p = 0; p < 5; p++) {
                aU[p] = make_float2(0.f, 0.f); aV[p] = make_float2(0.f, 0.f);
            }
#pragma unroll
            for (int p = 0; p < 5; p++) {
                aU[p] = ffma2(make_float2(x.x, x.x), wu[0][p], aU[p]);
                aU[p] = ffma2(make_float2(x.y, x.y), wu[1][p], aU[p]);
                aU[p] = ffma2(make_float2(x.z, x.z), wu[2][p], aU[p]);
                aU[p] = ffma2(make_float2(x.w, x.w), wu[3][p], aU[p]);
                aV[p] = ffma2(make_float2(x.x, x.x), wv[0][p], aV[p]);
                aV[p] = ffma2(make_float2(x.y, x.y), wv[1][p], aV[p]);
                aV[p] = ffma2(make_float2(x.z, x.z), wv[2][p], aV[p]);
                aV[p] = ffma2(make_float2(x.w, x.w), wv[3][p], aV[p]);
            }
            float a[20];
#pragma unroll
            for (int p = 0; p < 5; p++) {
                a[2 * p] = aU[p].x;      a[2 * p + 1] = aU[p].y;
                a[10 + 2 * p] = aV[p].x; a[10 + 2 * p + 1] = aV[p].y;
            }
            // reduction: xor16 (10), xor8 (5), xor4 (3), xor2 (2), xor1 (1)
            float t10[10];
#pragma unroll
            for (int k = 0; k < 10; k++) {
                float v = b4h ? a[k] : a[k + 10];
                float r = shx(v, 16);
                t10[k] = (b4h ? a[k + 10] : a[k]) + r;
            }
            float s5[5];
#pragma unroll
            for (int k = 0; k < 5; k++) {
                float v = b3h ? t10[k] : t10[k + 5];
                float r = shx(v, 8);
                s5[k] = (b3h ? t10[k + 5] : t10[k]) + r;
            }
            float u0, u1, u2;
            {
                float v, r;
                v = b2h ? s5[0] : s5[3]; r = shx(v, 4);
                u0 = (b2h ? s5[3] : s5[0]) + r;
                v = b2h ? s5[1] : s5[4]; r = shx(v, 4);
                u1 = (b2h ? s5[4] : s5[1]) + r;
                v = b2h ? s5[2] : 0.f;   r = shx(v, 4);
                u2 = b2h ? 0.f : (s5[2] + r);
            }
            float w0, w1;
            {
                float v, r;
                v = b1h ? u0 : (b2h ? u1 : u2); r = shx(v, 2);
                w0 = (b1h ? (b2h ? u1 : u2) : u0) + r;
                v = (b1h && !b2h) ? u1 : 0.f;   r = shx(v, 2);
                w1 = (!b1h && !b2h) ? (u1 + r) : 0.f;
            }
            float z;
            {
                bool two = (!b2h && !b1h);
                float v = two ? (b0h ? w0 : w1) : w0;
                float r = shx(v, 1);
                z = (two ? (b0h ? w1 : w0) : w0) + r;
            }
            if (rep && n < n_nodes) g_P[(size_t)n * 32 + off] = z;
        }
#pragma unroll
        for (int i = 0; i < 4; i++) xc[i] = xn[i];
    }
}

// ===========================================================================
// Edge kernel. Warp tile = 4 edges. Lane l owns columns 4l..4l+3 of W_e
// (20 float2 in registers). 10-channel sum via 12-shfl butterfly; rep lanes
// add the L2-resident P gathers + bias and store.
// ===========================================================================
__global__ __launch_bounds__(128) void edge_kernel(
    const float* __restrict__ eh, const float* __restrict__ W_w,
    const float* __restrict__ W_b,
    const void* __restrict__ src_raw, const void* __restrict__ dst_raw,
    float* __restrict__ out, int n_edges) {
    int tid = threadIdx.x, lane = tid & 31;

    float2 w[4][5];
#pragma unroll
    for (int d = 0; d < 4; d++)
#pragma unroll
        for (int p = 0; p < 5; p++) {
            int col = 256 + 4 * lane + d;
            w[d][p] = make_float2(__ldg(W_w + (2 * p) * 384 + col),
                                  __ldg(W_w + (2 * p + 1) * 384 + col));
        }

    bool hi4 = lane & 16, hi3 = lane & 8, hi2 = lane & 4, hi1 = lane & 2,
         hi0 = lane & 1;
    int ch  = (hi4 ? 5 : 0) +
              (hi3 ? (hi2 ? 4 : 3) : (hi2 ? 2 : (hi1 ? 1 : 0)));
    bool rep = (!hi0) && ((hi2 || hi3) ? !hi1 : true);
    float myb = __ldg(W_b + ch);
    int is64 = g_idx_is64;

    int T = (n_edges + 3) >> 2;
    int gw = (blockIdx.x * 128 + tid) >> 5;
    int stride = (gridDim.x * 128) >> 5;
    int maxF4 = n_edges * 32 - 1;
    const float4* ep = (const float4*)eh;

    int t = gw;
    float4 xc[4];
    if (t < T) {
#pragma unroll
        for (int i = 0; i < 4; i++)
            xc[i] = __ldg(ep + min(t * 128 + i * 32 + lane, maxF4));
    }
    for (; t < T; t += stride) {
        int tn = t + stride;
        float4 xn[4];
        if (tn < T) {
#pragma unroll
            for (int i = 0; i < 4; i++)
                xn[i] = __ldg(ep + min(tn * 128 + i * 32 + lane, maxF4));
        }
#pragma unroll
        for (int i = 0; i < 4; i++) {
            int e = t * 4 + i;
            float4 x = xc[i];
            float2 acc[5];
#pragma unroll
            for (int p = 0; p < 5; p++) acc[p] = make_float2(0.f, 0.f);
#pragma unroll
            for (int p = 0; p < 5; p++) {
                acc[p] = ffma2(make_float2(x.x, x.x), w[0][p], acc[p]);
                acc[p] = ffma2(make_float2(x.y, x.y), w[1][p], acc[p]);
                acc[p] = ffma2(make_float2(x.z, x.z), w[2][p], acc[p]);
                acc[p] = ffma2(make_float2(x.w, x.w), w[3][p], acc[p]);
            }
            float a[10];
#pragma unroll
            for (int p = 0; p < 5; p++) {
                a[2 * p] = acc[p].x; a[2 * p + 1] = acc[p].y;
            }
            // reduction: xor16 (5), xor8 (3), xor4 (2), xor2 (1), xor1 (1)
            float t5[5];
#pragma unroll
            for (int k = 0; k < 5; k++) {
                float v = hi4 ? a[k] : a[k + 5];
                float r = shx(v, 16);
                t5[k] = (hi4 ? a[k + 5] : a[k]) + r;
            }
            float u0, u1, u2;
            {
                float v, r;
                v = hi3 ? t5[0] : t5[3]; r = shx(v, 8);
                u0 = (hi3 ? t5[3] : t5[0]) + r;
                v = hi3 ? t5[1] : t5[4]; r = shx(v, 8);
                u1 = (hi3 ? t5[4] : t5[1]) + r;
                v = hi3 ? t5[2] : 0.f;   r = shx(v, 8);
                u2 = hi3 ? 0.f : (t5[2] + r);
            }
            float w0, w1;
            {
                float v, r;
                v = hi2 ? u0 : (hi3 ? u1 : u2); r = shx(v, 4);
                w0 = (hi2 ? (hi3 ? u1 : u2) : u0) + r;
                v = (hi2 && !hi3) ? u1 : 0.f;   r = shx(v, 4);
                w1 = (!hi2 && !hi3) ? (u1 + r) : 0.f;
            }
            float z;
            {
                bool two = (!hi3 && !hi2);
                float v = two ? (hi1 ? w0 : w1) : w0;
                float r = shx(v, 2);
                z = (two ? (hi1 ? w1 : w0) : w0) + r;
            }
            z += shx(z, 1);

            if (rep && e < n_edges) {
                long long sN, dN;
                if (is64) {
                    sN = ((const long long*)src_raw)[e];
                    dN = ((const long long*)dst_raw)[e];
                } else {
                    sN = ((const int*)src_raw)[e];
                    dN = ((const int*)dst_raw)[e];
                }
                float pu = __ldg(g_P + (size_t)sN * 32 + ch);
                float pv = __ldg(g_P + (size_t)dN * 32 + 16 + ch);
                out[(size_t)e * 10 + ch] = z + pu + pv + myb;
            }
        }
#pragma unroll
        for (int i = 0; i < 4; i++) xc[i] = xn[i];
    }
}

// ---------------------------------------------------------------------------
// Inputs: h [100000,128] f32, edge_h [600000,1,128] f32, W_w [10,384] f32,
// W_b [10] f32, src [600000] int32/64, dst [600000] int32/64.
// Output: [600000,10] f32.
// ---------------------------------------------------------------------------
extern "C" void kernel_launch(void* const* d_in, const int* in_sizes, int n_in,
                              void* d_out, int out_size) {
    const float* h   = (const float*)d_in[0];
    const float* eh  = (const float*)d_in[1];
    const float* W_w = (const float*)d_in[2];
    const float* W_b = (const float*)d_in[3];
    const void*  src = d_in[4];
    const void*  dst = d_in[5];
    float*       out = (float*)d_out;

    int n_nodes = in_sizes[0] / 128;
    int n_edges = in_sizes[4];

    node_kernel<<<592, 128>>>(h, W_w, (const long long*)src, n_nodes);
    edge_kernel<<<2368, 128>>>(eh, W_w, W_b, src, dst, out, n_edges);
}